// round 16
// baseline (speedup 1.0000x reference)
#include <cuda_runtime.h>

#define MAXR 100.0f

__device__ __forceinline__ float tanh_fast(float x) {
    float r;
    asm("tanh.approx.f32 %0, %1;" : "=f"(r) : "f"(x));
    return r;
}

// Accurate fast tanh: 1 - 2/(1+e^{2s}).  ~1e-7 abs err. Saturates correctly.
__device__ __forceinline__ float tanh_exp(float s) {
    float e2 = __expf(2.0f * s);
    return 1.0f - __fdividef(2.0f, 1.0f + e2);
}

// Parity-folded warp add: even lanes end with full 32-lane sum of va,
// odd lanes with that of vb. 6 shfl+add instead of 10.
__device__ __forceinline__ float fold_add(float va, float vb, int bit) {
    float send = bit ? va : vb;
    float keep = bit ? vb : va;
    float r = keep + __shfl_xor_sync(0xffffffffu, send, 1);
    #pragma unroll
    for (int o = 2; o < 32; o <<= 1)
        r += __shfl_xor_sync(0xffffffffu, r, o);
    return r;
}

// ---------------------------------------------------------------------------
// R11 geometry (best proven: 512 thr, 32 px/block, grid 512, occupancy 4,
// single wave) + NEW epilogue.
//
// Math: logit_j = clip(-(1/64) sum_i z*tanh(z), -100, 100) with
// z_ij = ab*x_i - a*x_j, always <= 0. Using z*tanh(z) >= |z| - 0.2785 and
// sum_i |z_ij| >= |a|(|b|*sum|x| - 64|x_j|), channel j's logit clips to
// EXACTLY -100 unless |x_j| > theta = (|b|*sum|x| - 6420/|a|)/64.
// Only those "uncertain" j (typically 0-4 per pixel) get an exact logit,
// computed with all 32 lanes parallel over i (2 fma+2 tanh per lane +
// butterfly), merged by online softmax; the certain class enters as
// count*e^(-100-m). Empty mask -> out = mean(x) automatically.
// This replaces the 64-iteration serial tanh loop that ~half the warps
// were running (the hidden cost behind rounds 6-14's plateau).
// ---------------------------------------------------------------------------
__global__ __launch_bounds__(512, 4) void dsf_fused_kernel(
    const float* __restrict__ x,
    const float* __restrict__ wgt,
    const float* __restrict__ bias,
    float* __restrict__ out) {

    __shared__ float  tile[64 * 110];   // 28.2 KB
    __shared__ float2 sw2[576];         // (w_out0, w_out1) per [c][tap]

    const unsigned F = 0xffffffffu;
    int tid = threadIdx.x;
    int p0  = blockIdx.x * 32;
    int b   = p0 >> 12;
    int hw0 = p0 & 4095;
    int h   = hw0 >> 6;
    int w0  = hw0 & 63;                 // 0 or 32 -> float4 aligned
    const float* xb = x + b * 262144;

    // ---- Phase 1a: halo tile, 1536 items = (c, r, f), exactly 3/thread ----
    #pragma unroll
    for (int k = 0; k < 3; k++) {
        int q  = tid + k * 512;
        int c  = q / 24;
        int rm = q - c * 24;
        int r  = rm >> 3;
        int f  = rm & 7;
        int hh = h + r - 1;
        bool rowok = (unsigned)hh < 64u;
        const float* src = xb + c * 4096 + hh * 64;

        float4 v = make_float4(0.f, 0.f, 0.f, 0.f);
        if (rowok)
            v = *reinterpret_cast<const float4*>(src + w0 + f * 4);
        float* d = &tile[c * 110 + r * 36 + 1 + f * 4];
        d[0] = v.x; d[1] = v.y; d[2] = v.z; d[3] = v.w;

        if (f == 0) {
            float hv = 0.0f;
            if (rowok && w0 > 0) hv = src[w0 - 1];
            tile[c * 110 + r * 36] = hv;
        } else if (f == 7) {
            float hv = 0.0f;
            if (rowok && w0 + 32 < 64) hv = src[w0 + 32];
            tile[c * 110 + r * 36 + 33] = hv;
        }
    }
    // ---- Phase 1b: weights -> (o0,o1) float2 pairs ------------------------
    if (tid < 144) {
        const float4* gw = reinterpret_cast<const float4*>(wgt);
        float4 wa = gw[tid];
        float4 wb = gw[144 + tid];
        int e = tid * 4;
        sw2[e + 0] = make_float2(wa.x, wb.x);
        sw2[e + 1] = make_float2(wa.y, wb.y);
        sw2[e + 2] = make_float2(wa.z, wb.z);
        sw2[e + 3] = make_float2(wa.w, wb.w);
    }
    float b0 = __ldg(&bias[0]);
    float b1 = __ldg(&bias[1]);
    __syncthreads();

    int wid    = tid >> 5;              // warp -> pixels 2w, 2w+1
    int lane   = tid & 31;
    int parity = lane & 1;              // 0 -> pixel A, 1 -> pixel B
    int px0    = wid * 2;

    // ---- Phase 2: conv for BOTH pixels (shared window + weights) ----------
    float cA0 = 0.f, cA1 = 0.f, cB0 = 0.f, cB1 = 0.f;
    #pragma unroll
    for (int g = 0; g < 2; g++) {
        int c = lane + g * 32;
        const float*  t = &tile[c * 110];
        const float2* W = &sw2[c * 9];
        #pragma unroll
        for (int r = 0; r < 3; r++) {
            float2 p01 = *reinterpret_cast<const float2*>(&t[r * 36 + px0]);
            float2 p23 = *reinterpret_cast<const float2*>(&t[r * 36 + px0 + 2]);
            float2 W0 = W[r * 3 + 0];
            float2 W1 = W[r * 3 + 1];
            float2 W2 = W[r * 3 + 2];
            cA0 = fmaf(p01.x, W0.x, cA0);  cA1 = fmaf(p01.x, W0.y, cA1);
            cA0 = fmaf(p01.y, W1.x, cA0);  cA1 = fmaf(p01.y, W1.y, cA1);
            cA0 = fmaf(p23.x, W2.x, cA0);  cA1 = fmaf(p23.x, W2.y, cA1);
            cB0 = fmaf(p01.y, W0.x, cB0);  cB1 = fmaf(p01.y, W0.y, cB1);
            cB0 = fmaf(p23.x, W1.x, cB0);  cB1 = fmaf(p23.x, W1.y, cB1);
            cB0 = fmaf(p23.y, W2.x, cB0);  cB1 = fmaf(p23.y, W2.y, cB1);
        }
    }

    // ---- Channel values + parity-folded reductions ------------------------
    float xa0 = tile[lane * 110 + 37 + px0];         // pixel A, ch lane
    float xa1 = tile[(lane + 32) * 110 + 37 + px0];  // pixel A, ch lane+32
    float xb0 = tile[lane * 110 + 38 + px0];         // pixel B
    float xb1 = tile[(lane + 32) * 110 + 38 + px0];

    float ss = fold_add(xa0 + xa1, xb0 + xb1, parity);               // sum x
    float sa = fold_add(fabsf(xa0) + fabsf(xa1),
                        fabsf(xb0) + fabsf(xb1), parity);            // sum|x|
    float c0 = fold_add(cA0, cB0, parity);
    float c1 = fold_add(cA1, cB1, parity);

    // Per-parity: even lanes hold pixel A scalars, odd lanes pixel B.
    float alpha = MAXR * tanh_exp(c0 + b0);
    float beta  = MAXR * tanh_exp(c1 + b1);

    // ---- Epilogue: per-channel certainty screen + sparse exact logits -----
    #pragma unroll
    for (int p = 0; p < 2; p++) {
        float al   = __shfl_sync(F, alpha, p);
        float be   = __shfl_sync(F, beta,  p);
        float sa_p = __shfl_sync(F, sa, p);
        float ss_p = __shfl_sync(F, ss, p);
        float xj0  = p ? xb0 : xa0;      // this lane's channels (j, j+32)
        float xj1  = p ? xb1 : xa1;

        // j certain (logit exactly -100) iff |x_j| <= theta.
        float theta = (fabsf(be) * sa_p - __fdividef(6420.0f, fabsf(al)))
                      * (1.0f / 64.0f);
        unsigned m0 = __ballot_sync(F, fabsf(xj0) > theta);
        unsigned m1 = __ballot_sync(F, fabsf(xj1) > theta);

        float ab  = al * be;
        float ui0 = ab * xj0;            // u_i for this lane's i-channels
        float ui1 = ab * xj1;

        float mrun = -MAXR, num = 0.0f, den = 0.0f, sxu = 0.0f;
        int ncert = 64 - __popc(m0) - __popc(m1);

        #pragma unroll
        for (int wsel = 0; wsel < 2; wsel++) {
            unsigned mm = wsel ? m1 : m0;
            while (mm) {                 // warp-uniform loop
                int src = __ffs(mm) - 1;
                mm &= mm - 1;
                float xj  = __shfl_sync(F, wsel ? xj1 : xj0, src);
                float ncj = -al * xj;
                float z0  = ui0 + ncj;
                float z1  = ui1 + ncj;
                float part = fmaf(z0, tanh_fast(z0), z1 * tanh_fast(z1));
                #pragma unroll
                for (int o = 16; o > 0; o >>= 1)
                    part += __shfl_xor_sync(F, part, o);
                float l = fmaxf(part * (-1.0f / 64.0f), -MAXR);
                if (l > mrun) {          // warp-uniform branch
                    float sc = __expf(mrun - l);
                    num *= sc; den *= sc; mrun = l;
                }
                float e = __expf(l - mrun);
                num = fmaf(xj, e, num);
                den += e;
                sxu += xj;
            }
        }
        // Fold in the certain class (logit exactly -100).
        float ec = __expf(-MAXR - mrun);
        num = fmaf(ss_p - sxu, ec, num);
        den = fmaf((float)ncert, ec, den);

        if (lane == 0) out[p0 + px0 + p] = num / den;
    }
}

extern "C" void kernel_launch(void* const* d_in, const int* in_sizes, int n_in,
                              void* d_out, int out_size) {
    const float* x    = (const float*)d_in[0];
    const float* w    = (const float*)d_in[1];
    const float* bias = (const float*)d_in[2];
    float* out        = (float*)d_out;

    dsf_fused_kernel<<<512, 512>>>(x, w, bias, out);
}

// round 17
// speedup vs baseline: 2.5534x; 2.5534x over previous
#include <cuda_runtime.h>

#define MAXR 100.0f

__device__ __forceinline__ float tanh_fast(float x) {
    float r;
    asm("tanh.approx.f32 %0, %1;" : "=f"(r) : "f"(x));
    return r;
}

// Accurate fast tanh: 1 - 2/(1+e^{2s}).  ~1e-7 abs err. Saturates correctly.
__device__ __forceinline__ float tanh_exp(float s) {
    float e2 = __expf(2.0f * s);
    return 1.0f - __fdividef(2.0f, 1.0f + e2);
}

// Max of NONNEGATIVE floats via integer redux (bit order == value order).
// redux.sync.max.u32 is legal on sm_103 (integer redux = sm_80+); R14-proven.
__device__ __forceinline__ float warp_max_nn(float v) {
    unsigned r;
    asm("redux.sync.max.u32 %0, %1, 0xffffffff;"
        : "=r"(r) : "r"(__float_as_uint(v)));
    return __uint_as_float(r);
}

// Parity-folded warp add: even lanes end with full 32-lane sum of va,
// odd lanes with that of vb. 6 shfl+add instead of 10.
__device__ __forceinline__ float fold_add(float va, float vb, int bit) {
    float send = bit ? va : vb;
    float keep = bit ? vb : va;
    float r = keep + __shfl_xor_sync(0xffffffffu, send, 1);
    #pragma unroll
    for (int o = 2; o < 32; o <<= 1)
        r += __shfl_xor_sync(0xffffffffu, r, o);
    return r;
}

// Packed f32x2 helpers (Blackwell FFMA2 — only reachable via PTX).
__device__ __forceinline__ unsigned long long dup2(float v) {
    unsigned long long r;
    asm("mov.b64 %0, {%1, %1};" : "=l"(r) : "f"(v));
    return r;
}
__device__ __forceinline__ void fma2(unsigned long long& acc,
                                     unsigned long long v2,
                                     unsigned long long w2) {
    asm("fma.rn.f32x2 %0, %1, %2, %3;"
        : "=l"(acc) : "l"(v2), "l"(w2), "l"(acc));
}

// ---------------------------------------------------------------------------
// R11 geometry (best proven): per block = 32 consecutive same-row pixels,
// 512 threads = 16 warps x 2 adjacent pixels, grid 512 -> one wave at occ 4.
// Tile: tile[c*110 + r*36 + col]; col 0 = left halo, 1..32 centers, 33 right
// halo; 110/2 = 55 odd -> conflict-free LDS.64; row stride 36 even -> aligned.
// Conv accumulators are (out0,out1) f32x2 pairs: sw2's float2 weights load
// directly as b64 operands of fma.rn.f32x2 (12 FFMA -> 6 FFMA2 per (g,r)).
// Reductions: parity-folded adds; max|x| via redux.sync.max.u32.
// Screen C0: logit_j = -|a|*mean_i(|d|*tanh(|a d|)) <= 0 clipped at -100;
//   |a|*(|b|*mean|x| - max|x|) >= 101 ==> all logits clip -> softmax uniform
//   -> out = mean_c(x). Fallback: dense lane-parallel exact tanh path
//   (R16 established the failing set is bimodal: all-certain or all-uncertain,
//   so the dense loop is the right shape for it).
// ---------------------------------------------------------------------------
__global__ __launch_bounds__(512, 4) void dsf_fused_kernel(
    const float* __restrict__ x,
    const float* __restrict__ wgt,
    const float* __restrict__ bias,
    float* __restrict__ out) {

    __shared__ float  tile[64 * 110];   // 28.2 KB
    __shared__ float2 sw2[576];         // (w_out0, w_out1) per [c][tap]

    const unsigned F = 0xffffffffu;
    int tid = threadIdx.x;
    int p0  = blockIdx.x * 32;
    int b   = p0 >> 12;
    int hw0 = p0 & 4095;
    int h   = hw0 >> 6;
    int w0  = hw0 & 63;                 // 0 or 32 -> float4 aligned
    const float* xb = x + b * 262144;

    // ---- Phase 1a: halo tile, 1536 items = (c, r, f), exactly 3/thread ----
    #pragma unroll
    for (int k = 0; k < 3; k++) {
        int q  = tid + k * 512;
        int c  = q / 24;
        int rm = q - c * 24;
        int r  = rm >> 3;
        int f  = rm & 7;
        int hh = h + r - 1;
        bool rowok = (unsigned)hh < 64u;
        const float* src = xb + c * 4096 + hh * 64;

        float4 v = make_float4(0.f, 0.f, 0.f, 0.f);
        if (rowok)
            v = *reinterpret_cast<const float4*>(src + w0 + f * 4);
        float* d = &tile[c * 110 + r * 36 + 1 + f * 4];
        d[0] = v.x; d[1] = v.y; d[2] = v.z; d[3] = v.w;

        if (f == 0) {
            float hv = 0.0f;
            if (rowok && w0 > 0) hv = src[w0 - 1];
            tile[c * 110 + r * 36] = hv;
        } else if (f == 7) {
            float hv = 0.0f;
            if (rowok && w0 + 32 < 64) hv = src[w0 + 32];
            tile[c * 110 + r * 36 + 33] = hv;
        }
    }
    // ---- Phase 1b: weights -> (o0,o1) float2 pairs ------------------------
    if (tid < 144) {
        const float4* gw = reinterpret_cast<const float4*>(wgt);
        float4 wa = gw[tid];            // out0 floats
        float4 wb = gw[144 + tid];      // out1 floats
        int e = tid * 4;
        sw2[e + 0] = make_float2(wa.x, wb.x);
        sw2[e + 1] = make_float2(wa.y, wb.y);
        sw2[e + 2] = make_float2(wa.z, wb.z);
        sw2[e + 3] = make_float2(wa.w, wb.w);
    }
    float b0 = __ldg(&bias[0]);
    float b1 = __ldg(&bias[1]);
    __syncthreads();

    int wid    = tid >> 5;              // warp -> pixels 2w, 2w+1
    int lane   = tid & 31;
    int parity = lane & 1;              // 0 -> pixel A, 1 -> pixel B
    int px0    = wid * 2;

    // ---- Phase 2: conv for BOTH pixels, f32x2 accumulators ----------------
    unsigned long long accA = 0ull, accB = 0ull;   // (out0, out1) pairs
    const unsigned long long* W64 =
        reinterpret_cast<const unsigned long long*>(sw2);
    #pragma unroll
    for (int g = 0; g < 2; g++) {
        int c = lane + g * 32;
        const float* t = &tile[c * 110];
        const unsigned long long* W = W64 + c * 9;
        #pragma unroll
        for (int r = 0; r < 3; r++) {
            float2 p01 = *reinterpret_cast<const float2*>(&t[r * 36 + px0]);
            float2 p23 = *reinterpret_cast<const float2*>(&t[r * 36 + px0 + 2]);
            unsigned long long W0 = W[r * 3 + 0];
            unsigned long long W1 = W[r * 3 + 1];
            unsigned long long W2 = W[r * 3 + 2];
            unsigned long long d0 = dup2(p01.x);
            unsigned long long d1 = dup2(p01.y);
            unsigned long long d2 = dup2(p23.x);
            unsigned long long d3 = dup2(p23.y);
            fma2(accA, d0, W0);  fma2(accA, d1, W1);  fma2(accA, d2, W2);
            fma2(accB, d1, W0);  fma2(accB, d2, W1);  fma2(accB, d3, W2);
        }
    }
    float cA0, cA1, cB0, cB1;
    asm("mov.b64 {%0, %1}, %2;" : "=f"(cA0), "=f"(cA1) : "l"(accA));
    asm("mov.b64 {%0, %1}, %2;" : "=f"(cB0), "=f"(cB1) : "l"(accB));

    // ---- Channel values + reductions --------------------------------------
    float xa0 = tile[lane * 110 + 37 + px0];         // pixel A, ch lane
    float xa1 = tile[(lane + 32) * 110 + 37 + px0];  // pixel A, ch lane+32
    float xb0 = tile[lane * 110 + 38 + px0];         // pixel B
    float xb1 = tile[(lane + 32) * 110 + 38 + px0];

    float ss = fold_add(xa0 + xa1, xb0 + xb1, parity);
    float sa = fold_add(fabsf(xa0) + fabsf(xa1), fabsf(xb0) + fabsf(xb1), parity);
    float c0 = fold_add(cA0, cB0, parity);
    float c1 = fold_add(cA1, cB1, parity);
    float smA = warp_max_nn(fmaxf(fabsf(xa0), fabsf(xa1)));
    float smB = warp_max_nn(fmaxf(fabsf(xb0), fabsf(xb1)));
    float sm  = parity ? smB : smA;

    // Per-parity epilogue: even lanes hold pixel A scalars, odd pixel B.
    float alpha = MAXR * tanh_exp(c0 + b0);
    float beta  = MAXR * tanh_exp(c1 + b1);

    // ---- Screen C0 ---------------------------------------------------------
    bool ok = fabsf(alpha) * (fabsf(beta) * (sa * (1.0f / 64.0f)) - sm) >= 101.0f;
    if (lane < 2 && ok) out[p0 + px0 + lane] = ss * (1.0f / 64.0f);
    if (__all_sync(F, ok)) return;

    // ---- Exact path(s): dense lane-parallel tanh interaction + softmax ----
    #pragma unroll
    for (int p = 0; p < 2; p++) {
        if (__shfl_sync(F, (int)ok, p)) continue;
        float alpha_p = __shfl_sync(F, alpha, p);
        float beta_p  = __shfl_sync(F, beta, p);
        float xj0 = p ? xb0 : xa0;
        float xj1 = p ? xb1 : xa1;
        int   px  = px0 + p;

        float ab  = alpha_p * beta_p;
        float nc0 = -alpha_p * xj0;
        float nc1 = -alpha_p * xj1;
        const float* xc = &tile[37 + px];

        float acc0 = 0.0f, acc1 = 0.0f;
        #pragma unroll 8
        for (int i = 0; i < 64; i++) {
            float xi = xc[i * 110];     // LDS broadcast
            float z0 = fmaf(ab, xi, nc0);
            float z1 = fmaf(ab, xi, nc1);
            acc0 = fmaf(z0, tanh_fast(z0), acc0);
            acc1 = fmaf(z1, tanh_fast(z1), acc1);
        }

        float l0 = fminf(fmaxf(acc0 * (-1.0f / 64.0f), -MAXR), MAXR);
        float l1 = fminf(fmaxf(acc1 * (-1.0f / 64.0f), -MAXR), MAXR);

        float m = fmaxf(l0, l1);
        #pragma unroll
        for (int o = 16; o > 0; o >>= 1)
            m = fmaxf(m, __shfl_xor_sync(F, m, o));

        float e0 = __expf(l0 - m);
        float e1 = __expf(l1 - m);
        float num = fmaf(xj0, e0, xj1 * e1);
        float den = e0 + e1;
        #pragma unroll
        for (int o = 16; o > 0; o >>= 1) {
            num += __shfl_xor_sync(F, num, o);
            den += __shfl_xor_sync(F, den, o);
        }

        if (lane == 0) out[p0 + px] = num / den;
    }
}

extern "C" void kernel_launch(void* const* d_in, const int* in_sizes, int n_in,
                              void* d_out, int out_size) {
    const float* x    = (const float*)d_in[0];
    const float* w    = (const float*)d_in[1];
    const float* bias = (const float*)d_in[2];
    float* out        = (float*)d_out;

    dsf_fused_kernel<<<512, 512>>>(x, w, bias, out);
}